// round 12
// baseline (speedup 1.0000x reference)
#include <cuda_runtime.h>
#include <math.h>

#define W_IMG 512
#define H_IMG 512
#define MAX_N (32 * W_IMG * H_IMG)
#define MAX_WORDS (MAX_N / 64)
#define MAX_NODES (MAX_WORDS * 32)   // <=32 runs per 64-px word

// Run-indexed node arrays (L2-resident).
__device__ int   g_lab[MAX_NODES];   // UF parent (compressed to root by k_area)
__device__ int   g_ar[MAX_NODES];    // area: seeded with own run length by k_prep
__device__ float g_rsum[MAX_NODES];  // per-run sum of (b - x), filled by k_bce
__device__ unsigned long long g_bits[MAX_WORDS];
// 0 = sum_fg bce/(w+1), 2 = sum_fg w, 3 = N_fg, 4 = sum_all b, 5 = sum_fg b
__device__ double g_acc[6];

// ---------------------------------------------------------------------------
__device__ __forceinline__ int find_root(int x) {
    int p = g_lab[x];
    while (p != x) { x = p; p = g_lab[x]; }
    return p;
}

__device__ __forceinline__ void merge(int a, int b) {
    bool done = false;
    do {
        a = find_root(a);
        b = find_root(b);
        if (a < b) { int t = a; a = b; b = t; }
        if (a != b) {
            int old = atomicMin(&g_lab[a], b);
            done = (old == a);
            a = old;
        } else {
            done = true;
        }
    } while (!done);
}

// node id of the run CONTAINING set bit k of word w with starts mask st
__device__ __forceinline__ int node_of(int w, unsigned long long st, int k) {
    return (w << 5) + __popcll(st & ((2ull << k) - 1ull)) - 1;
}
// node id of the run STARTING at bit k
__device__ __forceinline__ int node_at(int w, unsigned long long st, int k) {
    return (w << 5) + __popcll(st & ((1ull << k) - 1ull));
}

__device__ __forceinline__ int run_len(unsigned long long m, int k) {
    unsigned long long inv = ~(m >> k);
    return inv ? (__ffsll((long long)inv) - 1) : (64 - k);
}

__device__ __forceinline__ double warp_sum(double v) {
#pragma unroll
    for (int off = 16; off > 0; off >>= 1)
        v += __shfl_down_sync(0xFFFFFFFFu, v, off);
    return v;
}

// ---------------------------------------------------------------------------
// k_prep: thread per quad; build word mask via shfl; init nodes at owned
// run starts (lab=self, ar=own run length, rsum=0).
// ---------------------------------------------------------------------------
__global__ void k_prep(const float* __restrict__ tgt, int nquad) {
    int t = blockIdx.x * blockDim.x + threadIdx.x;
    if (t < nquad) {
        int w = t >> 4;
        int b0 = (t & 15) << 2;
        float4 v = __ldg(&((const float4*)tgt)[t]);
        unsigned long long nib = 0ull;
        if (v.x > 0.f) nib |= 1ull;
        if (v.y > 0.f) nib |= 2ull;
        if (v.z > 0.f) nib |= 4ull;
        if (v.w > 0.f) nib |= 8ull;
        unsigned long long m = nib << b0;
        m |= __shfl_xor_sync(0xFFFFFFFFu, m, 1);
        m |= __shfl_xor_sync(0xFFFFFFFFu, m, 2);
        m |= __shfl_xor_sync(0xFFFFFFFFu, m, 4);
        m |= __shfl_xor_sync(0xFFFFFFFFu, m, 8);
        if ((t & 15) == 0) g_bits[w] = m;

        unsigned long long st = m & ~(m << 1);
        unsigned int s = (unsigned int)((st >> b0) & 0xFull);
        while (s) {
            int k = __ffs(s) - 1;
            s &= s - 1;
            int kk = b0 + k;
            int id = node_at(w, st, kk);
            g_lab[id] = id;
            g_ar[id] = run_len(m, kk);
            g_rsum[id] = 0.f;
        }
    }
    if (blockIdx.x == 0 && threadIdx.x < 6) g_acc[threadIdx.x] = 0.0;
}

// ---------------------------------------------------------------------------
// k_union: word-level bitmask merges (run-indexed node ids)
// ---------------------------------------------------------------------------
__global__ void k_union(int nwords) {
    int w = blockIdx.x * blockDim.x + threadIdx.x;
    if (w >= nwords) return;
    unsigned long long cur = g_bits[w];
    if (!cur) return;
    unsigned long long stc = cur & ~(cur << 1);
    int wx = w & 7;
    int wy = (w >> 3) & (H_IMG - 1);

    if (wx && (cur & 1ull)) {
        unsigned long long L = g_bits[w - 1];
        if (L >> 63) {
            unsigned long long stl = L & ~(L << 1);
            merge((w << 5), ((w - 1) << 5) + __popcll(stl) - 1);
        }
    }
    if (wy) {
        unsigned long long up = g_bits[w - 8];
        unsigned long long ov = cur & up;
        if (ov) {
            unsigned long long stu = up & ~(up << 1);
            unsigned long long need = ov & ~(ov << 1);
            while (need) {
                int k = __ffsll((long long)need) - 1;
                need &= need - 1;
                merge(node_of(w, stc, k), node_of(w - 8, stu, k));
            }
        }
    }
}

// ---------------------------------------------------------------------------
// k_area: thread per quad; owned run starts -> compress + add own length
// to root (only for non-root nodes; roots were seeded in k_prep).
// ---------------------------------------------------------------------------
__global__ void k_area(int nquad) {
    int t = blockIdx.x * blockDim.x + threadIdx.x;
    if (t >= nquad) return;
    int w = t >> 4;
    int b0 = (t & 15) << 2;
    unsigned long long m = __ldg(&g_bits[w]);
    unsigned long long st = m & ~(m << 1);
    unsigned int s = (unsigned int)((st >> b0) & 0xFull);
    if (!s) return;
    while (s) {
        int k = __ffs(s) - 1;
        s &= s - 1;
        int kk = b0 + k;
        int node = node_at(w, st, kk);
        int root = find_root(node);
        if (root != node) {
            g_lab[node] = root;                      // compress
            atomicAdd(&g_ar[root], run_len(m, kk));  // add own length
        }
    }
}

// ---------------------------------------------------------------------------
// k_bce: PURE STREAMING. Per 8 px: bits + 2x float4; per px branchless
// b = relu(x)+log1p(e^-|x|); run-piece sum of (b-x) flushed via one
// no-return float atomic to the L2-resident run-indexed g_rsum.
// NO gathers, NO dependent chains.
// ---------------------------------------------------------------------------
__global__ void k_bce(const float* __restrict__ in, int nseg8) {
    float fAll = 0.f, fFg = 0.f;
    int t = blockIdx.x * blockDim.x + threadIdx.x;
    if (t < nseg8) {
        const float4* in4 = (const float4*)in;
        int w = t >> 3;                  // 8 segments of 8 px per word
        int kk0 = (t & 7) << 3;
        int q0 = t * 2;

        unsigned long long m = __ldg(&g_bits[w]);
        float4 v0 = __ldg(&in4[q0]);
        float4 v1 = __ldg(&in4[q0 + 1]);

        unsigned int fgb = (unsigned int)((m >> kk0) & 0xFFull);
        unsigned long long st = m & ~(m << 1);
        int wbase = w << 5;
        float xs[8] = {v0.x, v0.y, v0.z, v0.w, v1.x, v1.y, v1.z, v1.w};

        float piece = 0.f;
#pragma unroll
        for (int l = 0; l < 8; l++) {
            float x = xs[l];
            float gpl = __logf(1.f + __expf(-fabsf(x)));
            float b = gpl + fmaxf(x, 0.f);
            fAll += b;
            float sel = (float)((fgb >> l) & 1u);
            fFg += sel * b;
            piece += sel * (b - x);
            // flush at end of fg stretch (or at segment end)
            bool fg = (fgb >> l) & 1u;
            bool nxt = (l < 7) && ((fgb >> (l + 1)) & 1u);
            if (fg && !nxt) {
                int kk = kk0 + l;
                int nid = wbase + __popcll(st & ((2ull << kk) - 1ull)) - 1;
                atomicAdd(&g_rsum[nid], piece);
                piece = 0.f;
            }
        }
    }

    double d4 = fAll, d5 = fFg;
    __shared__ double sh[2][8];
    int lane = threadIdx.x & 31;
    int warp = threadIdx.x >> 5;
    d4 = warp_sum(d4); d5 = warp_sum(d5);
    if (lane == 0) { sh[0][warp] = d4; sh[1][warp] = d5; }
    __syncthreads();
    if (warp == 0) {
        int nw = blockDim.x >> 5;
        double v4 = (lane < nw) ? sh[0][lane] : 0.0;
        double v5 = (lane < nw) ? sh[1][lane] : 0.0;
        v4 = warp_sum(v4); v5 = warp_sum(v5);
        if (lane == 0) {
            atomicAdd(&g_acc[4], v4);
            atomicAdd(&g_acc[5], v5);
        }
    }
}

// ---------------------------------------------------------------------------
// k_post: 8 threads per word, strided over the word's run slots (avg 6.7
// runs/word -> ~1 run/thread, parallel 2-hop). f0 += rsum/(sqrt(a)+1);
// roots add a^1.5 (f2) and a (f3).
// ---------------------------------------------------------------------------
__global__ void k_post(int nwords) {
    double d0 = 0.0, d2 = 0.0, d3 = 0.0;
    int t = blockIdx.x * blockDim.x + threadIdx.x;
    int w = t >> 3;
    int j = t & 7;
    if (w < nwords) {
        unsigned long long m = __ldg(&g_bits[w]);
        if (m) {
            unsigned long long st = m & ~(m << 1);
            int ns = __popcll(st);
            int wbase = w << 5;
            float f0 = 0.f, f2 = 0.f, f3 = 0.f;
            for (int r = j; r < ns; r += 8) {
                int nid = wbase + r;
                float rs = __ldg(&g_rsum[nid]);
                int root = __ldg(&g_lab[nid]);        // compressed
                float a = (float)__ldg(&g_ar[root]);
                float sq = sqrtf(a);
                f0 += rs * __fdividef(1.f, sq + 1.f);
                if (root == nid) { f2 += a * sq; f3 += a; }
            }
            d0 = f0; d2 = f2; d3 = f3;
        }
    }

    __shared__ double sh[3][8];
    int lane = threadIdx.x & 31;
    int warp = threadIdx.x >> 5;
    d0 = warp_sum(d0); d2 = warp_sum(d2); d3 = warp_sum(d3);
    if (lane == 0) { sh[0][warp] = d0; sh[1][warp] = d2; sh[2][warp] = d3; }
    __syncthreads();
    if (warp == 0) {
        int nw = blockDim.x >> 5;
        double v0 = (lane < nw) ? sh[0][lane] : 0.0;
        double v2 = (lane < nw) ? sh[1][lane] : 0.0;
        double v3 = (lane < nw) ? sh[2][lane] : 0.0;
        v0 = warp_sum(v0); v2 = warp_sum(v2); v3 = warp_sum(v3);
        if (lane == 0) {
            atomicAdd(&g_acc[0], v0);
            atomicAdd(&g_acc[2], v2);
            atomicAdd(&g_acc[3], v3);
        }
    }
}

__global__ void k_final(float* __restrict__ out, double inv_n) {
    double nfg = g_acc[3];
    double mean_nz = g_acc[2] / (nfg > 0.0 ? nfg : 1.0);
    double f1 = g_acc[4] - g_acc[5];   // Σ_bg b = Σ_all b - Σ_fg b
    double loss = (g_acc[0] + f1 / (mean_nz + 1.0)) * inv_n;
    out[0] = (float)loss;
}

// ---------------------------------------------------------------------------
extern "C" void kernel_launch(void* const* d_in, const int* in_sizes, int n_in,
                              void* d_out, int out_size) {
    const float* inputs  = (const float*)d_in[0];
    const float* targets = (const float*)d_in[1];
    float* out = (float*)d_out;

    int n = in_sizes[0];
    int nwords = n >> 6;
    int nquad = n >> 2;
    int nseg8 = n >> 3;
    const int threads = 256;
    int qblocks = (nquad + threads - 1) / threads;
    int wblocks = (nwords + threads - 1) / threads;
    int sblocks = (nseg8 + threads - 1) / threads;
    int pblocks = (nwords * 8 + threads - 1) / threads;

    k_prep<<<qblocks, threads>>>(targets, nquad);
    k_union<<<wblocks, threads>>>(nwords);
    k_area<<<qblocks, threads>>>(nquad);
    k_bce<<<sblocks, threads>>>(inputs, nseg8);
    k_post<<<pblocks, threads>>>(nwords);
    k_final<<<1, 1>>>(out, 1.0 / (double)n);
}